// round 12
// baseline (speedup 1.0000x reference)
#include <cuda_runtime.h>
#include <math.h>
#include <stdint.h>

// NuclearLattice: D=3, W=64 -> box [-32,32]^3, spin in [-0.5,0.5]
// V0=10, VS=2, A_RANGE=2, KC=1.44, EPS=1e-6, PAULI_D2=1e-6.
// gauss = exp(-d2/4) = ex2(d2n) with d2n = -CSCL*d2; d2 = d2n*KINV.

#define TPB  128
#define TILE 128

#define CSCL 0.36067376f     // 0.25 * log2(e)
#define KINV (-2.7725887f)   // -1/CSCL = -4*ln(2)

__device__ double       g_acc     = 0.0;
__device__ int          g_blocked = 0;
__device__ unsigned int g_done    = 0;

#define EX2(d, a) \
    asm("ex2.approx.f32 %0, %1;" : "=f"(d) : "f"(a))
#define RSQ(d, a) \
    asm("rsqrt.approx.f32 %0, %1;" : "=f"(d) : "f"(a))

// ---- off-diag uniform fast path: 4 independent j-chains per iteration.
// Accumulates sum(g) and sum(r) separately; coef/cq applied once by caller.
template<bool COUL, bool PAULI>
__device__ __forceinline__ void fast_off(
    const float4* __restrict__ sa,      // {x2c, y2c, z2c, w=-C*psq}
    float xi, float yi, float zi, float npsqi,
    float* sg,      // [4] gauss partial sums
    float* sr,      // [4] rsqrt partial sums
    float* pmax)    // [4] pauli max trackers
{
    #pragma unroll 8
    for (int p = 0; p < TILE / 4; p++) {
        float t[4];
        #pragma unroll
        for (int c = 0; c < 4; c++) {
            const float4 a = sa[4 * p + c];
            t[c] = fmaf(a.x, xi, fmaf(a.y, yi, fmaf(a.z, zi, a.w))) + npsqi;
        }
        #pragma unroll
        for (int c = 0; c < 4; c++) {
            float g;
            EX2(g, t[c]);
            sg[c] += g;
        }
        if (COUL) {
            #pragma unroll
            for (int c = 0; c < 4; c++) {
                const float v = fmaxf(fmaf(t[c], KINV, 1e-6f), 1e-6f);
                float r;
                RSQ(r, v);
                sr[c] += r;
            }
        }
        if (PAULI) {
            #pragma unroll
            for (int c = 0; c < 4; c++)
                pmax[c] = fmaxf(pmax[c], t[c]);
        }
    }
}

// ---- scalar diag fast path (uniform tile) ----
template<bool COUL>
__device__ __forceinline__ void fast_diag(
    const float4* __restrict__ sa,
    float xi, float yi, float zi, float npsqi,
    float coef, float cq, float thr, int tid, float& acc, int& pcount)
{
    #pragma unroll 8
    for (int jj = 0; jj < TILE; jj++) {
        const float4 a = sa[jj];
        const float d2n = fmaf(a.x, xi, fmaf(a.y, yi, fmaf(a.z, zi, a.w))) + npsqi;
        float g;
        EX2(g, d2n);
        float e = coef * g;
        if (COUL) {
            const float v = fmaxf(fmaf(d2n, KINV, 1e-6f), 1e-6f);
            float r;
            RSQ(r, v);
            e = fmaf(cq, r, e);
        }
        if (jj != tid) {                        // exclude self pair
            acc += e;
            pcount += (d2n > thr) ? 1 : 0;
        }
    }
}

// ---- general fallback: exact per-pair spin/charge (any data) ----
template<bool DIAG>
__device__ __forceinline__ void gen_loop(
    const float4* __restrict__ sa,
    const float2* __restrict__ sb,              // {sp, q}
    float xi, float yi, float zi, float npsqi,
    float spi, float qi, int tid,
    float& acc, float& pmin, int& pcount)
{
    #pragma unroll 4
    for (int jj = 0; jj < TILE; jj++) {
        const float4 a = sa[jj];
        const float2 b = sb[jj];
        const float d2n = fmaf(a.x, xi, fmaf(a.y, yi, fmaf(a.z, zi, a.w))) + npsqi;
        const float d2  = fmaxf(d2n * KINV, 0.0f);
        const float dsp = spi - b.x;
        const float dq  = qi  - b.y;
        const float d2c = fmaf(dsp, dsp, fmaf(dq, dq, d2));
        float g;
        EX2(g, d2n);
        const float coef = fmaf(2.0f * spi, b.x, -10.0f);
        float r;
        RSQ(r, d2 + 1e-6f);
        const float cq = 1.44f * qi * b.y;
        const float e  = fmaf(coef, g, cq * r);
        if (DIAG) {
            if (jj != tid) { acc += e; pcount += (d2c < 1e-6f) ? 1 : 0; }
        } else {
            acc += e; pmin = fminf(pmin, d2c);
        }
    }
}

__global__ __launch_bounds__(TPB) void nl_kernel(
    const float* __restrict__ states, int A, int nblocks, float* __restrict__ out)
{
    // Decode triangular block index k -> (bx <= by)
    const int k = blockIdx.x;
    int by = (int)((sqrtf(8.0f * (float)k + 1.0f) - 1.0f) * 0.5f);
    while ((by + 1) * (by + 2) / 2 <= k) by++;
    while (by * (by + 1) / 2 > k)       by--;
    const int bx = k - by * (by + 1) / 2;
    const bool diag = (bx == by);

    __shared__ float4 sa[TILE];
    __shared__ float2 sb[TILE];
    __shared__ float4 uref;              // {sp_i0, q_i0, sp_j0, q_j0}

    const int tid = threadIdx.x;

    // i-atom; padding far away with zero spin/charge
    const int i = bx * TILE + tid;
    const bool vi = (i < A);
    float xi = 1e18f, yi = 1e18f, zi = 1e18f, spi = 0.0f, qi = 0.0f;
    if (vi) {
        const float* s = states + (size_t)i * 5;
        xi = s[0]; yi = s[1]; zi = s[2]; spi = s[3]; qi = s[4] + 0.5f;
    }
    const float npsqi = -CSCL * fmaf(xi, xi, fmaf(yi, yi, zi * zi));

    // bounds check once per atom (each atom appears in exactly one diag block)
    if (diag && vi) {
        const bool bad = (xi  < -32.0f) || (xi  > 32.0f) ||
                         (yi  < -32.0f) || (yi  > 32.0f) ||
                         (zi  < -32.0f) || (zi  > 32.0f) ||
                         (spi < -0.5f)  || (spi > 0.5f);
        if (bad) atomicOr(&g_blocked, 1);
    }

    // j-tile -> smem; keep j (sp,q) in regs for the uniformity check
    const int j = by * TILE + tid;
    const bool vj = (j < A);
    float jsp = 0.0f, jq = 0.0f;
    {
        float x = -1e18f, y = -1e18f, z = -1e18f;
        if (vj) {
            const float* s = states + (size_t)j * 5;
            x = s[0]; y = s[1]; z = s[2]; jsp = s[3]; jq = s[4] + 0.5f;
        }
        const float psq = fmaf(x, x, fmaf(y, y, z * z));
        sa[tid] = make_float4(2.0f * CSCL * x, 2.0f * CSCL * y,
                              2.0f * CSCL * z, -CSCL * psq);
        sb[tid] = make_float2(jsp, jq);
    }
    if (tid == 0) uref = make_float4(spi, qi, jsp, jq);
    __syncthreads();

    // tile-pair uniformity: all valid atoms match the first atom of their tile
    bool myuni = (!vi || (spi == uref.x && qi == uref.y)) &&
                 (!vj || (jsp == uref.z && jq == uref.w));
    const int unified = __syncthreads_and(myuni ? 1 : 0);

    float acc    = 0.0f;
    float pmin   = 1e30f;
    int   pcount = 0;
    bool  pauli  = false;

    if (unified) {
        const float coef = fmaf(2.0f * uref.x, uref.z, -10.0f);  // -V0 + VS*sp_i*sp_j
        const float cq   = 1.44f * uref.y * uref.w;              // KC*q_i*q_j
        const float dsp  = uref.x - uref.z;
        const float dq   = uref.y - uref.w;
        const float dcc  = fmaf(dsp, dsp, dq * dq);
        const bool  coul = (cq != 0.0f);
        const bool  pact = (dcc < 1e-6f);                        // pauli possible at all
        const float thr  = -(1e-6f - dcc) * CSCL;                // d2n > thr <=> d2+dcc < 1e-6

        if (diag) {
            if (coul) fast_diag<true >(sa, xi, yi, zi, npsqi, coef, cq, thr, tid, acc, pcount);
            else      fast_diag<false>(sa, xi, yi, zi, npsqi, coef, cq, thr, tid, acc, pcount);
            pauli = (pcount > 0);
        } else {
            float sg[4]   = {0.0f, 0.0f, 0.0f, 0.0f};
            float sr[4]   = {0.0f, 0.0f, 0.0f, 0.0f};
            float pmax[4] = {-1e30f, -1e30f, -1e30f, -1e30f};
            if      ( coul &&  pact) fast_off<true,  true >(sa, xi, yi, zi, npsqi, sg, sr, pmax);
            else if ( coul && !pact) fast_off<true,  false>(sa, xi, yi, zi, npsqi, sg, sr, pmax);
            else if (!coul &&  pact) fast_off<false, true >(sa, xi, yi, zi, npsqi, sg, sr, pmax);
            else                     fast_off<false, false>(sa, xi, yi, zi, npsqi, sg, sr, pmax);
            const float G = (sg[0] + sg[1]) + (sg[2] + sg[3]);
            const float R = (sr[0] + sr[1]) + (sr[2] + sr[3]);
            acc = fmaf(coef, G, cq * R);
            pauli = pact &&
                (fmaxf(fmaxf(pmax[0], pmax[1]), fmaxf(pmax[2], pmax[3])) > thr);
        }
    } else {
        if (diag) {
            gen_loop<true >(sa, sb, xi, yi, zi, npsqi, spi, qi, tid, acc, pmin, pcount);
            pauli = (pcount > 0);
        } else {
            gen_loop<false>(sa, sb, xi, yi, zi, npsqi, spi, qi, tid, acc, pmin, pcount);
            pauli = (pmin < 1e-6f);
        }
    }

    if (diag) acc *= 0.5f;                  // diag tiles counted both orders
    if (pauli) atomicOr(&g_blocked, 1);

    // fp32 per-thread -> double warp -> block (4 warps) -> one atomic
    double v = (double)acc;
    #pragma unroll
    for (int off = 16; off > 0; off >>= 1)
        v += __shfl_down_sync(0xffffffffu, v, off);

    __shared__ double wsum[TPB / 32];
    const int lane = tid & 31;
    const int warp = tid >> 5;
    if (lane == 0) wsum[warp] = v;
    __syncthreads();

    if (tid == 0) {
        v = wsum[0] + wsum[1] + wsum[2] + wsum[3];
        atomicAdd(&g_acc, v);
        __threadfence();
        const unsigned t = atomicAdd(&g_done, 1u);
        if (t == (unsigned)nblocks - 1u) {
            // Last block: publish result and reset state for next graph replay
            const double e  = atomicAdd(&g_acc, 0.0);
            const int    bl = atomicOr(&g_blocked, 0);
            out[0] = bl ? INFINITY : (float)e;
            g_acc     = 0.0;
            g_blocked = 0;
            __threadfence();
            g_done = 0;
        }
    }
}

extern "C" void kernel_launch(void* const* d_in, const int* in_sizes, int n_in,
                              void* d_out, int out_size) {
    const float* states = (const float*)d_in[0];
    const int A = in_sizes[0] / 5;

    const int tiles   = (A + TILE - 1) / TILE;
    const int nblocks = tiles * (tiles + 1) / 2;

    nl_kernel<<<nblocks, TPB>>>(states, A, nblocks, (float*)d_out);
}

// round 13
// speedup vs baseline: 1.0407x; 1.0407x over previous
#include <cuda_runtime.h>
#include <math.h>
#include <stdint.h>

// NuclearLattice: D=3, W=64 -> box [-32,32]^3, spin in [-0.5,0.5]
// V0=10, VS=2, A_RANGE=2, KC=1.44, EPS=1e-6, PAULI_D2=1e-6.
// gauss = exp(-d2/4) = ex2(d2n) with d2n = -CSCL*d2; d2 = d2n*KINV.

#define TPB  128
#define TILE 128

#define CSCL 0.36067376f     // 0.25 * log2(e)
#define KINV (-2.7725887f)   // -1/CSCL = -4*ln(2)

__device__ double       g_acc     = 0.0;
__device__ int          g_blocked = 0;
__device__ unsigned int g_done    = 0;

#define EX2(d, a) \
    asm("ex2.approx.f32 %0, %1;" : "=f"(d) : "f"(a))
#define RSQ(d, a) \
    asm("rsqrt.approx.f32 %0, %1;" : "=f"(d) : "f"(a))
// One guaranteed 16-byte shared load (broadcast across the warp).
#define LDS4(a, b, c, d, addr) \
    asm("ld.shared.v4.f32 {%0, %1, %2, %3}, [%4];" \
        : "=f"(a), "=f"(b), "=f"(c), "=f"(d) : "r"(addr))

// ---- off-diag uniform fast path: 2 independent j-chains, wide LDS ----
template<bool COUL, bool PAULI>
__device__ __forceinline__ void fast_off(
    uint32_t sab,                       // shared addr of sa[0]
    float xi, float yi, float zi, float npsqi,
    float coef, float cq,
    float& acc0, float& acc1, float& pmax0, float& pmax1)
{
    #pragma unroll 8
    for (int p = 0; p < TILE / 2; p++) {
        float ax0, ay0, az0, aw0, ax1, ay1, az1, aw1;
        LDS4(ax0, ay0, az0, aw0, sab + p * 32);
        LDS4(ax1, ay1, az1, aw1, sab + p * 32 + 16);

        const float t0 = fmaf(ax0, xi, fmaf(ay0, yi, fmaf(az0, zi, aw0))) + npsqi;
        const float t1 = fmaf(ax1, xi, fmaf(ay1, yi, fmaf(az1, zi, aw1))) + npsqi;

        float g0, g1;
        EX2(g0, t0);
        EX2(g1, t1);
        acc0 = fmaf(coef, g0, acc0);
        acc1 = fmaf(coef, g1, acc1);

        if (COUL) {
            const float v0 = fmaxf(fmaf(t0, KINV, 1e-6f), 1e-6f);
            const float v1 = fmaxf(fmaf(t1, KINV, 1e-6f), 1e-6f);
            float r0, r1;
            RSQ(r0, v0);
            RSQ(r1, v1);
            acc0 = fmaf(cq, r0, acc0);
            acc1 = fmaf(cq, r1, acc1);
        }
        if (PAULI) {
            pmax0 = fmaxf(pmax0, t0);
            pmax1 = fmaxf(pmax1, t1);
        }
    }
}

// ---- scalar diag fast path (uniform tile), wide LDS ----
template<bool COUL>
__device__ __forceinline__ void fast_diag(
    uint32_t sab,
    float xi, float yi, float zi, float npsqi,
    float coef, float cq, float thr, int tid, float& acc, int& pcount)
{
    #pragma unroll 8
    for (int jj = 0; jj < TILE; jj++) {
        float ax, ay, az, aw;
        LDS4(ax, ay, az, aw, sab + jj * 16);
        const float d2n = fmaf(ax, xi, fmaf(ay, yi, fmaf(az, zi, aw))) + npsqi;
        float g;
        EX2(g, d2n);
        float e = coef * g;
        if (COUL) {
            const float v = fmaxf(fmaf(d2n, KINV, 1e-6f), 1e-6f);
            float r;
            RSQ(r, v);
            e = fmaf(cq, r, e);
        }
        if (jj != tid) {                        // exclude self pair
            acc += e;
            pcount += (d2n > thr) ? 1 : 0;
        }
    }
}

// ---- general fallback: exact per-pair spin/charge (any data) ----
template<bool DIAG>
__device__ __forceinline__ void gen_loop(
    const float4* __restrict__ sa,
    const float2* __restrict__ sb,              // {sp, q}
    float xi, float yi, float zi, float npsqi,
    float spi, float qi, int tid,
    float& acc, float& pmin, int& pcount)
{
    #pragma unroll 4
    for (int jj = 0; jj < TILE; jj++) {
        const float4 a = sa[jj];
        const float2 b = sb[jj];
        const float d2n = fmaf(a.x, xi, fmaf(a.y, yi, fmaf(a.z, zi, a.w))) + npsqi;
        const float d2  = fmaxf(d2n * KINV, 0.0f);
        const float dsp = spi - b.x;
        const float dq  = qi  - b.y;
        const float d2c = fmaf(dsp, dsp, fmaf(dq, dq, d2));
        float g;
        EX2(g, d2n);
        const float coef = fmaf(2.0f * spi, b.x, -10.0f);
        float r;
        RSQ(r, d2 + 1e-6f);
        const float cq = 1.44f * qi * b.y;
        const float e  = fmaf(coef, g, cq * r);
        if (DIAG) {
            if (jj != tid) { acc += e; pcount += (d2c < 1e-6f) ? 1 : 0; }
        } else {
            acc += e; pmin = fminf(pmin, d2c);
        }
    }
}

__global__ __launch_bounds__(TPB) void nl_kernel(
    const float* __restrict__ states, int A, int nblocks, float* __restrict__ out)
{
    // Decode triangular block index k -> (bx <= by)
    const int k = blockIdx.x;
    int by = (int)((sqrtf(8.0f * (float)k + 1.0f) - 1.0f) * 0.5f);
    while ((by + 1) * (by + 2) / 2 <= k) by++;
    while (by * (by + 1) / 2 > k)       by--;
    const int bx = k - by * (by + 1) / 2;
    const bool diag = (bx == by);

    __shared__ float4 sa[TILE];
    __shared__ float2 sb[TILE];
    __shared__ float4 uref;              // {sp_i0, q_i0, sp_j0, q_j0}

    const int tid = threadIdx.x;

    // i-atom; padding far away with zero spin/charge
    const int i = bx * TILE + tid;
    const bool vi = (i < A);
    float xi = 1e18f, yi = 1e18f, zi = 1e18f, spi = 0.0f, qi = 0.0f;
    if (vi) {
        const float* s = states + (size_t)i * 5;
        xi = s[0]; yi = s[1]; zi = s[2]; spi = s[3]; qi = s[4] + 0.5f;
    }
    const float npsqi = -CSCL * fmaf(xi, xi, fmaf(yi, yi, zi * zi));

    // bounds check once per atom (each atom appears in exactly one diag block)
    if (diag && vi) {
        const bool bad = (xi  < -32.0f) || (xi  > 32.0f) ||
                         (yi  < -32.0f) || (yi  > 32.0f) ||
                         (zi  < -32.0f) || (zi  > 32.0f) ||
                         (spi < -0.5f)  || (spi > 0.5f);
        if (bad) atomicOr(&g_blocked, 1);
    }

    // j-tile -> smem; keep j (sp,q) in regs for the uniformity check
    const int j = by * TILE + tid;
    const bool vj = (j < A);
    float jsp = 0.0f, jq = 0.0f;
    {
        float x = -1e18f, y = -1e18f, z = -1e18f;
        if (vj) {
            const float* s = states + (size_t)j * 5;
            x = s[0]; y = s[1]; z = s[2]; jsp = s[3]; jq = s[4] + 0.5f;
        }
        const float psq = fmaf(x, x, fmaf(y, y, z * z));
        sa[tid] = make_float4(2.0f * CSCL * x, 2.0f * CSCL * y,
                              2.0f * CSCL * z, -CSCL * psq);
        sb[tid] = make_float2(jsp, jq);
    }
    if (tid == 0) uref = make_float4(spi, qi, jsp, jq);
    __syncthreads();

    // tile-pair uniformity: all valid atoms match the first atom of their tile
    bool myuni = (!vi || (spi == uref.x && qi == uref.y)) &&
                 (!vj || (jsp == uref.z && jq == uref.w));
    const int unified = __syncthreads_and(myuni ? 1 : 0);

    const uint32_t sab = (uint32_t)__cvta_generic_to_shared(sa);

    float acc    = 0.0f;
    float accB   = 0.0f;
    float pmaxA  = -1e30f, pmaxB = -1e30f;
    float pmin   = 1e30f;
    int   pcount = 0;
    bool  pauli  = false;

    if (unified) {
        const float coef = fmaf(2.0f * uref.x, uref.z, -10.0f);  // -V0 + VS*sp_i*sp_j
        const float cq   = 1.44f * uref.y * uref.w;              // KC*q_i*q_j
        const float dsp  = uref.x - uref.z;
        const float dq   = uref.y - uref.w;
        const float dcc  = fmaf(dsp, dsp, dq * dq);
        const bool  coul = (cq != 0.0f);
        const bool  pact = (dcc < 1e-6f);                        // pauli possible at all
        const float thr  = -(1e-6f - dcc) * CSCL;                // d2n > thr <=> d2+dcc < 1e-6

        if (diag) {
            if (coul) fast_diag<true >(sab, xi, yi, zi, npsqi, coef, cq, thr, tid, acc, pcount);
            else      fast_diag<false>(sab, xi, yi, zi, npsqi, coef, cq, thr, tid, acc, pcount);
            pauli = (pcount > 0);
        } else {
            if      ( coul &&  pact) fast_off<true,  true >(sab, xi, yi, zi, npsqi, coef, cq, acc, accB, pmaxA, pmaxB);
            else if ( coul && !pact) fast_off<true,  false>(sab, xi, yi, zi, npsqi, coef, cq, acc, accB, pmaxA, pmaxB);
            else if (!coul &&  pact) fast_off<false, true >(sab, xi, yi, zi, npsqi, coef, cq, acc, accB, pmaxA, pmaxB);
            else                     fast_off<false, false>(sab, xi, yi, zi, npsqi, coef, cq, acc, accB, pmaxA, pmaxB);
            acc += accB;
            pauli = pact && (fmaxf(pmaxA, pmaxB) > thr);
        }
    } else {
        if (diag) {
            gen_loop<true >(sa, sb, xi, yi, zi, npsqi, spi, qi, tid, acc, pmin, pcount);
            pauli = (pcount > 0);
        } else {
            gen_loop<false>(sa, sb, xi, yi, zi, npsqi, spi, qi, tid, acc, pmin, pcount);
            pauli = (pmin < 1e-6f);
        }
    }

    if (diag) acc *= 0.5f;                  // diag tiles counted both orders
    if (pauli) atomicOr(&g_blocked, 1);

    // fp32 per-thread -> double warp -> block (4 warps) -> one atomic
    double v = (double)acc;
    #pragma unroll
    for (int off = 16; off > 0; off >>= 1)
        v += __shfl_down_sync(0xffffffffu, v, off);

    __shared__ double wsum[TPB / 32];
    const int lane = tid & 31;
    const int warp = tid >> 5;
    if (lane == 0) wsum[warp] = v;
    __syncthreads();

    if (tid == 0) {
        v = wsum[0] + wsum[1] + wsum[2] + wsum[3];
        atomicAdd(&g_acc, v);
        __threadfence();
        const unsigned t = atomicAdd(&g_done, 1u);
        if (t == (unsigned)nblocks - 1u) {
            // Last block: publish result and reset state for next graph replay
            const double e  = atomicAdd(&g_acc, 0.0);
            const int    bl = atomicOr(&g_blocked, 0);
            out[0] = bl ? INFINITY : (float)e;
            g_acc     = 0.0;
            g_blocked = 0;
            __threadfence();
            g_done = 0;
        }
    }
}

extern "C" void kernel_launch(void* const* d_in, const int* in_sizes, int n_in,
                              void* d_out, int out_size) {
    const float* states = (const float*)d_in[0];
    const int A = in_sizes[0] / 5;

    const int tiles   = (A + TILE - 1) / TILE;
    const int nblocks = tiles * (tiles + 1) / 2;

    nl_kernel<<<nblocks, TPB>>>(states, A, nblocks, (float*)d_out);
}